// round 8
// baseline (speedup 1.0000x reference)
#include <cuda_runtime.h>
#include <math.h>

#define B_ 32
#define S_ 64
#define T_ 64
#define H_ 256
#define K3 768
#define SOS 1
#define NBLK 128
#define NTHR 256
#define NLINE 32
#define LSTRIDE 64   // 64 u32 = 256B between counter lines

// ---------------- device scratch ----------------
__device__ float g_hT[2][H_ * B_];          // hidden state [j][b], double-buffered
__device__ float g_hB[B_ * H_];             // hidden state row-major [b][j]
__device__ float g_xT_all[S_ * H_ * B_];    // encoder inputs [t][j][b]
__device__ float g_giE[S_ * K3 * B_];       // precomputed encoder gi [t][k][b]
__device__ float g_xT[H_ * B_];             // decoder x [j'][b]
__device__ float g_ctx[H_ * B_];            // attention context [jj][b]
__device__ float g_EB[B_ * S_ * H_];        // encoder outputs [b][s][j]
__device__ float g_c0[H_];
__device__ float g_probs[B_ * T_];
__device__ __align__(128) unsigned int g_bar_count = 0;   // legacy gen barrier (self-cleaning)
__device__ __align__(128) unsigned int g_bar_gen = 0;
// distributed sync counter arrays: 32 lines x 256B
__device__ __align__(256) unsigned int g_barA[NLINE * LSTRIDE];
__device__ __align__(256) unsigned int g_ctxA[NLINE * LSTRIDE];
__device__ __align__(256) unsigned int g_xA[NLINE * LSTRIDE];
__device__ __align__(256) unsigned int g_hA[NLINE * LSTRIDE];

__device__ __forceinline__ float wred(float v) {
#pragma unroll
    for (int o = 16; o > 0; o >>= 1) v += __shfl_xor_sync(0xffffffffu, v, o);
    return v;
}
__device__ __forceinline__ float wmax(float v) {
#pragma unroll
    for (int o = 16; o > 0; o >>= 1) v = fmaxf(v, __shfl_xor_sync(0xffffffffu, v, o));
    return v;
}

__device__ __forceinline__ void arrive(unsigned int* arr, int line) {
    asm volatile("red.release.gpu.global.add.u32 [%0], 1;" :: "l"(arr + line * LSTRIDE) : "memory");
}
// executed by FULL warp 0 only: lane l polls line l
__device__ __forceinline__ void wait_lines(unsigned int* arr, unsigned int target) {
    if (target == 0) return;
    unsigned int* p = arr + (threadIdx.x & 31) * LSTRIDE;
    for (;;) {
        unsigned int v;
        asm volatile("ld.acquire.gpu.global.u32 %0, [%1];" : "=r"(v) : "l"(p));
        if (__all_sync(0xffffffffu, (int)(v - target) >= 0)) break;
    }
}

// legacy self-cleaning barrier (init syncs only; safe across graph replays)
__device__ __forceinline__ void gen_barrier() {
    __syncthreads();
    if (threadIdx.x == 0) {
        unsigned gen;
        asm volatile("ld.acquire.gpu.global.u32 %0, [%1];" : "=r"(gen) : "l"(&g_bar_gen));
        unsigned old;
        asm volatile("atom.release.gpu.global.add.u32 %0, [%1], %2;"
                     : "=r"(old) : "l"(&g_bar_count), "r"(1u) : "memory");
        if (old == NBLK - 1) {
            asm volatile("st.relaxed.gpu.global.u32 [%0], %1;" :: "l"(&g_bar_count), "r"(0u) : "memory");
            asm volatile("st.release.gpu.global.u32 [%0], %1;" :: "l"(&g_bar_gen), "r"(gen + 1u) : "memory");
        } else {
            unsigned cur;
            do { asm volatile("ld.acquire.gpu.global.u32 %0, [%1];" : "=r"(cur) : "l"(&g_bar_gen)); }
            while (cur == gen);
        }
    }
    __syncthreads();
}

// distributed full barrier over all 128 blocks (4 arrivals per line)
__device__ __forceinline__ void dist_barrier(unsigned int nb) {
    __syncthreads();
    if ((threadIdx.x >> 5) == 0) {
        if ((threadIdx.x & 31) == 0) arrive(g_barA, blockIdx.x & 31);
        wait_lines(g_barA, 4u * nb);
    }
    __syncthreads();
}

__device__ __forceinline__ void stage32KB(float* dst, const float* src, int tid) {
    const float4* s4 = (const float4*)src;
    float4* d4 = (float4*)dst;
    for (int i = tid; i < (H_ * B_) / 4; i += NTHR) d4[i] = __ldcg(s4 + i);
}

__device__ __forceinline__ float2 dot2(const float4* __restrict__ p0, const float4* __restrict__ p1,
                                       const float* __restrict__ sv, int lane, float b0, float b1) {
    float a0a = b0, a0b = 0.f, a1a = b1, a1b = 0.f;
#pragma unroll 8
    for (int q = 0; q < 64; q++) {
        float4 wa = __ldg(p0 + q);
        float4 wb = __ldg(p1 + q);
        int base = q * 128 + lane;
        float h0 = sv[base], h1 = sv[base + 32], h2 = sv[base + 64], h3 = sv[base + 96];
        a0a += wa.x * h0; a0b += wa.y * h1; a0a += wa.z * h2; a0b += wa.w * h3;
        a1a += wb.x * h0; a1b += wb.y * h1; a1a += wb.z * h2; a1b += wb.w * h3;
    }
    return make_float2(a0a + a0b, a1a + a1b);
}

__device__ __forceinline__ float dot1(const float4* __restrict__ p0,
                                      const float* __restrict__ sv, int lane, float b0) {
    float a0 = b0, a1 = 0.f;
#pragma unroll 8
    for (int q = 0; q < 64; q++) {
        float4 wa = __ldg(p0 + q);
        int base = q * 128 + lane;
        a0 += wa.x * sv[base];      a1 += wa.y * sv[base + 32];
        a0 += wa.z * sv[base + 64]; a1 += wa.w * sv[base + 96];
    }
    return a0 + a1;
}

__global__ void __launch_bounds__(NTHR, 1)
seq2seq_kernel(const int* __restrict__ ctx_tok, const int* __restrict__ inp_tok,
               const int* __restrict__ tsamp,
               const float* __restrict__ enc_emb,
               const float* __restrict__ enc_Wih, const float* __restrict__ enc_Whh,
               const float* __restrict__ enc_bih, const float* __restrict__ enc_bhh,
               const float* __restrict__ dec_emb,
               const float* __restrict__ W_comb, const float* __restrict__ b_comb,
               const float* __restrict__ dec_Wih, const float* __restrict__ dec_Whh,
               const float* __restrict__ dec_bih, const float* __restrict__ dec_bhh,
               const float* __restrict__ W_out, const float* __restrict__ b_out,
               float* __restrict__ out)
{
    extern __shared__ float sm[];
    float* sE   = sm;             // 16384: enc_outs (attn blocks)
    float* sh   = sm + 16384;     // 8192
    float* sx   = sm + 24576;     // 8192
    float* sgi  = sm + 32768;     // 384
    float* sgh  = sm + 33152;     // 384
    float* shb  = sm + 33536;     // 256
    float* satt = sm + 33792;     // 64
    float* sred = sm + 33856;     // 32

    const int tid  = threadIdx.x;
    const int lane = tid & 31;
    const int w    = tid >> 5;       // warp 0..7
    const int bx   = blockIdx.x;

    // ---- encoder row mapping: warps 0..5 do 1 row each ----
    const int gE = w >> 1;
    const int pE = w & 1;
    const int jE = bx * 2 + pE;
    const int kE = (w < 6) ? (gE * H_ + jE) : 0;
    const float4* whE = (const float4*)(enc_Whh + (size_t)kE * H_);
    const float bhE = enc_bhh[kE];

    // ---- decoder GRU mapping (bx < 64): 12 rows; warps 0-3: 2 rows, warps 4-7: 1 row ----
    int lrA = 0; bool twoRows = false;
    if (w < 4) { lrA = 2 * w; twoRows = true; } else { lrA = 8 + (w - 4); }
    const int lrB = lrA + 1;
    const int gA = lrA >> 2, jlA = lrA & 3;
    const float4 *whD0 = nullptr, *whD1 = nullptr, *wiD0 = nullptr, *wiD1 = nullptr;
    float bhD0 = 0.f, bhD1 = 0.f, biD0 = 0.f, biD1 = 0.f;
    if (bx < 64) {
        const int k0 = gA * H_ + bx * 4 + jlA;     // rows lrA, lrA+1 are k0, k0+1 (same gate)
        const int k1 = k0 + 1;
        whD0 = (const float4*)(dec_Whh + (size_t)k0 * H_);
        whD1 = (const float4*)(dec_Whh + (size_t)k1 * H_);
        wiD0 = (const float4*)(dec_Wih + (size_t)k0 * H_);
        wiD1 = (const float4*)(dec_Wih + (size_t)k1 * H_);
        bhD0 = dec_bhh[k0]; bhD1 = dec_bhh[k1];
        biD0 = dec_bih[k0]; biD1 = dec_bih[k1];
    }

    // ---------------- init (parallel) ----------------
    for (int i = bx * NTHR + tid; i < NLINE * LSTRIDE; i += NBLK * NTHR) {
        g_barA[i] = 0u; g_ctxA[i] = 0u; g_xA[i] = 0u; g_hA[i] = 0u;
    }
    for (int i = bx * NTHR + tid; i < H_ * B_; i += NBLK * NTHR) g_hT[0][i] = 0.f;

    for (int i = bx * NTHR + tid; i < S_ * B_ * H_; i += NBLK * NTHR) {
        int jj = i & (H_ - 1);
        int tb = i >> 8;
        int b  = tb & (B_ - 1);
        int t  = tb >> 5;
        int tok = ctx_tok[b * S_ + t];
        g_xT_all[(t * H_ + jj) * B_ + b] = enc_emb[(size_t)tok * H_ + jj];
    }
    {   // c0[j'] = b_comb[j'] + W_comb[j', 0:H] . dec_emb[SOS]   (blocks 0..31)
        int gw = bx * 8 + w;
        if (gw < H_) {
            float s = 0.f;
#pragma unroll
            for (int m = 0; m < 8; m++) {
                int jj = lane + 32 * m;
                s += __ldg(&W_comb[(size_t)gw * (2 * H_) + jj]) * __ldg(&dec_emb[SOS * H_ + jj]);
            }
            s = wred(s);
            if (lane == 0) g_c0[gw] = s + b_comb[gw];
        }
    }
    gen_barrier();

    // ---------------- encoder gi precompute (parallel) ----------------
    {
        const int t  = bx >> 1;
        const int kh = (bx & 1) * 384;
        stage32KB(sh, g_xT_all + (size_t)t * H_ * B_, tid);
        __syncthreads();
        for (int i = 0; i < 24; i++) {       // 8 warps x 24 pairs = 384 rows
            int k0 = kh + w * 48 + 2 * i;
            int k1 = k0 + 1;
            const float4* pA = (const float4*)(enc_Wih + (size_t)k0 * H_);
            const float4* pB = (const float4*)(enc_Wih + (size_t)k1 * H_);
            float2 r = dot2(pA, pB, sh, lane, enc_bih[k0], enc_bih[k1]);
            g_giE[((size_t)t * K3 + k0) * B_ + lane] = r.x;
            g_giE[((size_t)t * K3 + k1) * B_ + lane] = r.y;
        }
    }
    gen_barrier();

    int buf = 0;
    unsigned nb = 0;   // dist-barrier index

    // ---------------- encoder: 64 steps, 1 distributed barrier each ----------------
    for (int t = 0; t < S_; t++) {
        float gi0 = 0.f, gi1 = 0.f, gi2 = 0.f;
        if (w < 2) {
            const float* gp = g_giE + ((size_t)t * K3 + (bx * 2 + w)) * B_ + lane;
            gi0 = __ldcg(gp);
            gi1 = __ldcg(gp + 256 * B_);
            gi2 = __ldcg(gp + 512 * B_);
        }
        stage32KB(sh, g_hT[buf], tid);
        __syncthreads();

        if (w < 6) sgh[w * 32 + lane] = dot1(whE, sh, lane, bhE);
        __syncthreads();

        if (w < 2) {
            int j = bx * 2 + w;
            float r = 1.f / (1.f + expf(-(gi0 + sgh[w * 32 + lane])));
            float z = 1.f / (1.f + expf(-(gi1 + sgh[(2 + w) * 32 + lane])));
            float n = tanhf(gi2 + r * sgh[(4 + w) * 32 + lane]);
            float hold = sh[j * B_ + lane];
            float hn = (1.f - z) * n + z * hold;
            g_hT[buf ^ 1][j * B_ + lane] = hn;
            g_EB[((size_t)lane * S_ + t) * H_ + j] = hn;
            g_hB[lane * H_ + j] = hn;
        }
        buf ^= 1;
        nb++; dist_barrier(nb);
        if (bx >= 64) {   // attn blocks progressively stage enc_outs row t
            int b = (bx - 64) >> 1;
            const float4* src = (const float4*)(g_EB + ((size_t)b * S_ + t) * H_);
            float4* dst = (float4*)(sE + t * H_);
            if (tid < 64) dst[tid] = __ldcg(src + tid);
        }
    }

    // ---------------- decoder: 64 steps, 3 distributed flags each ----------------
    for (int t = 0; t < T_; t++) {
        // h(t-1..) ready: 2 arrivals/line per completed step
        if (w == 0) wait_lines(g_hA, 2u * (unsigned)t);
        __syncthreads();

        if (bx < 64) {
            // ---- GRU path ----
            stage32KB(sh, g_hT[buf], tid);
            __syncthreads();
            if (twoRows) {
                float2 gh = dot2(whD0, whD1, sh, lane, bhD0, bhD1);
                sgh[lrA * 32 + lane] = gh.x;
                sgh[lrB * 32 + lane] = gh.y;
            } else {
                sgh[lrA * 32 + lane] = dot1(whD0, sh, lane, bhD0);
            }
            // wait ctx
            if (w == 0) wait_lines(g_ctxA, 2u * (unsigned)(t + 1));
            __syncthreads();
            stage32KB(sx, g_ctx, tid);
            __syncthreads();
            if (w < 4) {   // x rows jp = bx*4 + w
                int jp = bx * 4 + w;
                const float4* wc = (const float4*)(W_comb + (size_t)jp * (2 * H_) + H_);
                float xv = dot1(wc, sx, lane, g_c0[jp]);
                g_xT[jp * B_ + lane] = xv > 0.f ? xv : 0.f;
            }
            __syncthreads();
            if (w == 0) {
                if (lane == 0) arrive(g_xA, bx & 31);
                wait_lines(g_xA, 2u * (unsigned)(t + 1));
            }
            __syncthreads();
            stage32KB(sx, g_xT, tid);
            __syncthreads();
            if (twoRows) {
                float2 gi = dot2(wiD0, wiD1, sx, lane, biD0, biD1);
                sgi[lrA * 32 + lane] = gi.x;
                sgi[lrB * 32 + lane] = gi.y;
            } else {
                sgi[lrA * 32 + lane] = dot1(wiD0, sx, lane, biD0);
            }
            __syncthreads();
            if (w < 4) {
                int j = bx * 4 + w;
                float r = 1.f / (1.f + expf(-(sgi[w * 32 + lane] + sgh[w * 32 + lane])));
                float z = 1.f / (1.f + expf(-(sgi[(4 + w) * 32 + lane] + sgh[(4 + w) * 32 + lane])));
                float n = tanhf(sgi[(8 + w) * 32 + lane] + r * sgh[(8 + w) * 32 + lane]);
                float hold = sh[j * B_ + lane];
                float hn = (1.f - z) * n + z * hold;
                g_hT[buf ^ 1][j * B_ + lane] = hn;
                g_hB[lane * H_ + j] = hn;
            }
            __syncthreads();
            if (tid == 0) arrive(g_hA, bx & 31);
        } else {
            // ---- attention path: b = (bx-64)>>1, half = (bx-64)&1 ----
            const int bxa = bx - 64, b = bxa >> 1, half = bxa & 1;
            if (tid < 64) ((float4*)shb)[tid] = __ldcg(((const float4*)(g_hB + b * H_)) + tid);
            __syncthreads();
            for (int s = w; s < S_; s += 8) {
                float p = 0.f;
#pragma unroll
                for (int m = 0; m < 8; m++) { int jj = lane + 32 * m; p += sE[s * H_ + jj] * shb[jj]; }
                p = wred(p);
                if (lane == 0) satt[s] = p;
            }
            __syncthreads();
            if (w == 0) {
                float v0 = satt[lane], v1 = satt[lane + 32];
                float mx = wmax(fmaxf(v0, v1));
                float e0 = expf(v0 - mx), e1 = expf(v1 - mx);
                float ssum = wred(e0 + e1);
                satt[lane] = e0 / ssum; satt[lane + 32] = e1 / ssum;
            }
            if (w == 1 && half == 1 && t > 0) {
                int tok = inp_tok[b * T_ + (t - 1)];
                float p = 0.f;
#pragma unroll
                for (int m = 0; m < 8; m++) { int jj = lane + 32 * m; p += shb[jj] * __ldg(&W_out[(size_t)tok * H_ + jj]); }
                p = wred(p);
                if (lane == 0) g_probs[b * T_ + (t - 1)] = 1.f / (1.f + expf(-(p + b_out[tok])));
            }
            __syncthreads();
            if (tid < 128) {
                int jj = half * 128 + tid;
                float c = 0.f;
#pragma unroll 8
                for (int s = 0; s < S_; s++) c += satt[s] * sE[s * H_ + jj];
                g_ctx[jj * B_ + b] = c;
            }
            __syncthreads();
            if (tid == 0) arrive(g_ctxA, bxa & 31);
        }
        buf ^= 1;
    }

    // ---------------- final-step prob ----------------
    if (bx >= 64 && ((bx - 64) & 1) == 1) {
        const int b = (bx - 64) >> 1;
        if (w == 0) wait_lines(g_hA, 2u * (unsigned)T_);
        __syncthreads();
        if (tid < 64) ((float4*)shb)[tid] = __ldcg(((const float4*)(g_hB + b * H_)) + tid);
        __syncthreads();
        if (w == 0) {
            int tok = inp_tok[b * T_ + (T_ - 1)];
            float p = 0.f;
#pragma unroll
            for (int m = 0; m < 8; m++) { int jj = lane + 32 * m; p += shb[jj] * __ldg(&W_out[(size_t)tok * H_ + jj]); }
            p = wred(p);
            if (lane == 0) g_probs[b * T_ + (T_ - 1)] = 1.f / (1.f + expf(-(p + b_out[tok])));
        }
    }
    nb++; dist_barrier(nb);

    // ---------------- outputs ----------------
    for (int i = bx * NTHR + tid; i < B_ * T_; i += NBLK * NTHR) out[1 + i] = __ldcg(g_probs + i);
    if (bx == 0) {
        float tv = tsamp ? (float)(*tsamp) : 1.0f;
        float acc = 0.f;
        for (int i = tid; i < B_ * T_; i += NTHR) {
            float p  = __ldcg(g_probs + i);
            float lp = fmaxf(logf(p), -100.f);
            float l1 = fmaxf(log1pf(-p), -100.f);
            acc += tv * lp + (1.f - tv) * l1;
        }
        acc = wred(acc);
        if (lane == 0) sred[w] = acc;
        __syncthreads();
        if (tid == 0) {
            float s = 0.f;
            for (int u = 0; u < 8; u++) s += sred[u];
            out[0] = -s / (float)(B_ * T_);
        }
    }
}

extern "C" void kernel_launch(void* const* d_in, const int* in_sizes, int n_in,
                              void* d_out, int out_size) {
    (void)in_sizes; (void)out_size;
    const size_t smem = 33888 * sizeof(float);   // 135552 B
    cudaFuncSetAttribute(seq2seq_kernel, cudaFuncAttributeMaxDynamicSharedMemorySize, (int)smem);

    int base = (n_in >= 17) ? 3 : 2;
    const int* ts = (n_in >= 17) ? (const int*)d_in[2] : nullptr;

    seq2seq_kernel<<<NBLK, NTHR, smem>>>(
        (const int*)d_in[0], (const int*)d_in[1], ts,
        (const float*)d_in[base + 0],  // enc_emb
        (const float*)d_in[base + 1],  // enc_Wih
        (const float*)d_in[base + 2],  // enc_Whh
        (const float*)d_in[base + 3],  // enc_bih
        (const float*)d_in[base + 4],  // enc_bhh
        (const float*)d_in[base + 5],  // dec_emb
        (const float*)d_in[base + 6],  // W_comb
        (const float*)d_in[base + 7],  // b_comb
        (const float*)d_in[base + 8],  // dec_Wih
        (const float*)d_in[base + 9],  // dec_Whh
        (const float*)d_in[base + 10], // dec_bih
        (const float*)d_in[base + 11], // dec_bhh
        (const float*)d_in[base + 12], // W_out
        (const float*)d_in[base + 13], // b_out
        (float*)d_out);
}